// round 15
// baseline (speedup 1.0000x reference)
#include <cuda_runtime.h>
#include <cuda_bf16.h>
#include <math.h>
#include <stdint.h>

#define B_   1024
#define S_   1024
#define D_   2048
#define E_   2048
#define OUTW 8192

#define TM 64
#define TN 64
#define KC 16
#define NSTAGE 3
// stage: A_hi 2KB + A_lo 2KB + B_hi 2KB + B_lo 2KB = 8KB
#define ATILE 2048u
#define BTILE 2048u
#define SB_H  (2u * ATILE)
#define SB_L  (2u * ATILE + BTILE)
#define STG   (2u * ATILE + 2u * BTILE)
#define SMEMB ((int)(NSTAGE * STG))      // 24KB -> 5 CTA/SM

// ---------------- device scratch ----------------
__device__ __align__(128) __nv_bfloat16 g_Wp1h[2048u*2048u], g_Wp1l[2048u*2048u];
__device__ __align__(128) __nv_bfloat16 g_Wih [6144u*2048u], g_Wil [6144u*2048u];
__device__ __align__(128) __nv_bfloat16 g_Whh [6144u*2048u], g_Whl [6144u*2048u];
__device__ __align__(128) __nv_bfloat16 g_Wp2h[2048u*2048u], g_Wp2l[2048u*2048u];
__device__ __align__(128) __nv_bfloat16 g_Wcph[2048u*2048u], g_Wcpl[2048u*2048u];
__device__ __align__(128) __nv_bfloat16 g_Wq1h[2048u*4096u], g_Wq1l[2048u*4096u];
__device__ __align__(128) __nv_bfloat16 g_Wq2h[2048u*2048u], g_Wq2l[2048u*2048u];
__device__ __align__(128) __nv_bfloat16 g_Wcqh[2048u*2048u], g_Wcql[2048u*2048u];
__device__ __align__(128) __nv_bfloat16 g_Xh [B_*2048u], g_Xl [B_*2048u];
__device__ __align__(128) __nv_bfloat16 g_Ph [B_*2048u], g_Pl [B_*2048u];
__device__ __align__(128) __nv_bfloat16 g_h1h[B_*2048u], g_h1l[B_*2048u];
__device__ __align__(128) __nv_bfloat16 g_dth[B_*2048u], g_dtl[B_*2048u];
__device__ __align__(128) __nv_bfloat16 g_h2h[B_*2048u], g_h2l[B_*2048u];
__device__ __align__(128) __nv_bfloat16 g_h2qh[B_*2048u], g_h2ql[B_*2048u];
__device__ __align__(128) __nv_bfloat16 g_Xqh[B_*4096u], g_Xql[B_*4096u];
__device__ __align__(128) __nv_bfloat16 g_dqh[B_*2048u], g_dql[B_*2048u];
__device__ __align__(128) float g_gi[B_*6144u];
__device__ __align__(128) float g_gh[B_*6144u];
__device__ __align__(128) float g_bcp[2048], g_ccp[2048], g_bcq[2048], g_ccq[2048];

// ---------------- helpers ----------------
__device__ __forceinline__ float sigmoidf_(float x) { return 1.0f / (1.0f + expf(-x)); }
__device__ __forceinline__ float softplusf_(float x) {
    return fmaxf(x, 0.0f) + log1pf(expf(-fabsf(x)));
}
__device__ __forceinline__ void split2(float v, __nv_bfloat16& h, __nv_bfloat16& l) {
    h = __float2bfloat16(v);
    l = __float2bfloat16(v - __bfloat162float(h));
}
__device__ __forceinline__ uint32_t smem_u32(const void* p) {
    uint32_t a;
    asm("{ .reg .u64 t; cvta.to.shared.u64 t, %1; cvt.u32.u64 %0, t; }" : "=r"(a) : "l"(p));
    return a;
}
__device__ __forceinline__ void cp16(uint32_t s, const void* g) {
    asm volatile("cp.async.cg.shared.global [%0], [%1], 16;" :: "r"(s), "l"(g));
}
__device__ __forceinline__ void cpcommit() { asm volatile("cp.async.commit_group;" ::: "memory"); }
__device__ __forceinline__ void cpwait1() { asm volatile("cp.async.wait_group 1;" ::: "memory"); }
__device__ __forceinline__ void cpwait0() { asm volatile("cp.async.wait_group 0;" ::: "memory"); }
__device__ __forceinline__ void ldm_x4(uint32_t* r, uint32_t addr) {
    asm volatile("ldmatrix.sync.aligned.m8n8.x4.shared.b16 {%0,%1,%2,%3}, [%4];"
                 : "=r"(r[0]), "=r"(r[1]), "=r"(r[2]), "=r"(r[3]) : "r"(addr));
}
__device__ __forceinline__ void mma_bf16(float* c, const uint32_t* a, const uint32_t* b) {
    asm volatile(
        "mma.sync.aligned.m16n8k16.row.col.f32.bf16.bf16.f32 "
        "{%0,%1,%2,%3}, {%4,%5,%6,%7}, {%8,%9}, {%0,%1,%2,%3};"
        : "+f"(c[0]), "+f"(c[1]), "+f"(c[2]), "+f"(c[3])
        : "r"(a[0]), "r"(a[1]), "r"(a[2]), "r"(a[3]), "r"(b[0]), "r"(b[1]));
}
// 64-row x 16-k bf16 tile, 32B rows, 2 swizzled 16B chunks per row
__device__ __forceinline__ uint32_t tadr(int row, int c) {
    return (uint32_t)(row * 32) + (uint32_t)((c ^ ((row >> 2) & 1)) << 4);
}

// ---------------- split-bf16 HMMA GEMM: 64x64, 128 thr, 5 CTA/SM ----------------
// epi: 0 fp32->Cf ; 1 relu->split bf16 (Chi,Clo) ; 2 fused mu/std -> Cf
__global__ void __launch_bounds__(128, 5) gemm_mma(
    const __nv_bfloat16* __restrict__ Ah, const __nv_bfloat16* __restrict__ Al,
    const __nv_bfloat16* __restrict__ Bh, const __nv_bfloat16* __restrict__ Bl,
    const float* __restrict__ bias, const float* __restrict__ csum,
    float* __restrict__ Cf, __nv_bfloat16* __restrict__ Chi, __nv_bfloat16* __restrict__ Clo,
    int K, int ldc, int epi)
{
    extern __shared__ __align__(1024) char smem[];
    const uint32_t sb = smem_u32(smem);
    const int tid = threadIdx.x;
    const int lane = tid & 31, wid = tid >> 5;
    const int wr = wid >> 1, wc = wid & 1;
    const int bm = blockIdx.y * TM;
    const int bn = blockIdx.x * TN;
    const int g = lane >> 3, i8 = lane & 7;

    float acc[2][4][4];
#pragma unroll
    for (int a = 0; a < 2; a++)
#pragma unroll
        for (int b = 0; b < 4; b++)
#pragma unroll
            for (int k = 0; k < 4; k++) acc[a][b][k] = 0.0f;

    // stage loader: 128 granules per plane (64 rows x 2 chunks), 1 per thread
    auto load_stage = [&](uint32_t sbase, int kpos) {
        const int row = tid >> 1, c = tid & 1;
        const uint32_t so = tadr(row, c);
        const size_t goA = (size_t)(bm + row) * K + kpos + c * 8;
        const size_t goB = (size_t)(bn + row) * K + kpos + c * 8;
        cp16(sbase + so, Ah + goA);
        cp16(sbase + ATILE + so, Al + goA);
        cp16(sbase + SB_H + so, Bh + goB);
        cp16(sbase + SB_L + so, Bl + goB);
        cpcommit();
    };

    load_stage(sb, 0);
    load_stage(sb + STG, KC);

    const int nk = K / KC;
    const int aRowBase = wr * 32 + (g & 1) * 8 + i8;
    const int aKsel = g >> 1;
    const int bRowBase = wc * 32 + (g >> 1) * 8 + i8;
    const int bKsel = g & 1;

    int bufc = 0, bufl = 2;
    for (int s = 0; s < nk; s++) {
        if (s < nk - 1) cpwait1(); else cpwait0();
        __syncthreads();
        if (s + 2 < nk) load_stage(sb + (uint32_t)bufl * STG, (s + 2) * KC);

        const uint32_t base = sb + (uint32_t)bufc * STG;
        const uint32_t bAh = base, bAl = base + ATILE;
        const uint32_t bBh = base + SB_H, bBl = base + SB_L;

        // one k16 step: 8 ldmatrix + 24 HMMA
        uint32_t Bfh[4][2], Bfl[4][2];
#pragma unroll
        for (int half = 0; half < 2; half++) {
            uint32_t r[4];
            int nrow = bRowBase + half * 16;
            ldm_x4(r, bBh + tadr(nrow, bKsel));
            Bfh[half * 2 + 0][0] = r[0]; Bfh[half * 2 + 0][1] = r[1];
            Bfh[half * 2 + 1][0] = r[2]; Bfh[half * 2 + 1][1] = r[3];
            ldm_x4(r, bBl + tadr(nrow, bKsel));
            Bfl[half * 2 + 0][0] = r[0]; Bfl[half * 2 + 0][1] = r[1];
            Bfl[half * 2 + 1][0] = r[2]; Bfl[half * 2 + 1][1] = r[3];
        }
#pragma unroll
        for (int am = 0; am < 2; am++) {
            uint32_t Afh[4], Afl[4];
            int arow = aRowBase + am * 16;
            ldm_x4(Afh, bAh + tadr(arow, aKsel));
            ldm_x4(Afl, bAl + tadr(arow, aKsel));
#pragma unroll
            for (int bnf = 0; bnf < 4; bnf++) mma_bf16(acc[am][bnf], Afh, Bfh[bnf]);
#pragma unroll
            for (int bnf = 0; bnf < 4; bnf++) mma_bf16(acc[am][bnf], Afh, Bfl[bnf]);
#pragma unroll
            for (int bnf = 0; bnf < 4; bnf++) mma_bf16(acc[am][bnf], Afl, Bfh[bnf]);
        }
        bufc = (bufc == 2) ? 0 : bufc + 1;
        bufl = (bufl == 2) ? 0 : bufl + 1;
    }

    const int rQ = lane >> 2;
    const int cP = (lane & 3) * 2;
#pragma unroll
    for (int am = 0; am < 2; am++) {
#pragma unroll
        for (int bnf = 0; bnf < 4; bnf++) {
            const int r0 = bm + wr * 32 + am * 16 + rQ;
            const int c  = bn + wc * 32 + bnf * 8 + cP;
            float v0 = acc[am][bnf][0] + bias[c];
            float v1 = acc[am][bnf][1] + bias[c + 1];
            float v2 = acc[am][bnf][2] + bias[c];
            float v3 = acc[am][bnf][3] + bias[c + 1];
            if (epi == 1) {
                v0 = fmaxf(v0, 0.0f); v1 = fmaxf(v1, 0.0f);
                v2 = fmaxf(v2, 0.0f); v3 = fmaxf(v3, 0.0f);
                __nv_bfloat16 h0,l0,h1,l1,h2,l2,h3,l3;
                split2(v0,h0,l0); split2(v1,h1,l1); split2(v2,h2,l2); split2(v3,h3,l3);
                __nv_bfloat162 p01; p01.x = h0; p01.y = h1;
                __nv_bfloat162 q01; q01.x = l0; q01.y = l1;
                __nv_bfloat162 p23; p23.x = h2; p23.y = h3;
                __nv_bfloat162 q23; q23.x = l2; q23.y = l3;
                *reinterpret_cast<__nv_bfloat162*>(Chi + (size_t)r0 * ldc + c) = p01;
                *reinterpret_cast<__nv_bfloat162*>(Clo + (size_t)r0 * ldc + c) = q01;
                *reinterpret_cast<__nv_bfloat162*>(Chi + (size_t)(r0 + 8) * ldc + c) = p23;
                *reinterpret_cast<__nv_bfloat162*>(Clo + (size_t)(r0 + 8) * ldc + c) = q23;
            } else {
                if (epi == 2 && c >= S_) {
                    const float cs0 = csum[c], cs1 = csum[c + 1];
                    v0 = softplusf_(v0 + cs0) + 1e-4f;
                    v1 = softplusf_(v1 + cs1) + 1e-4f;
                    v2 = softplusf_(v2 + cs0) + 1e-4f;
                    v3 = softplusf_(v3 + cs1) + 1e-4f;
                }
                float2 w01; w01.x = v0; w01.y = v1;
                float2 w23; w23.x = v2; w23.y = v3;
                *reinterpret_cast<float2*>(Cf + (size_t)r0 * ldc + c) = w01;
                *reinterpret_cast<float2*>(Cf + (size_t)(r0 + 8) * ldc + c) = w23;
            }
        }
    }
}

// ---------------- transpose + split (vectorized) ----------------
__global__ void transpose_split(const float* __restrict__ W, int K, int N,
                                __nv_bfloat16* __restrict__ Th, __nv_bfloat16* __restrict__ Tl,
                                int ldT, int roff)
{
    __shared__ float t[64][33];
    const int n0 = blockIdx.x * 32, k0 = blockIdx.y * 64;
    const int tx = threadIdx.x, ty = threadIdx.y;
#pragma unroll
    for (int r = 0; r < 64; r += 8)
        t[ty + r][tx] = W[(size_t)(k0 + ty + r) * N + n0 + tx];
    __syncthreads();
#pragma unroll
    for (int r = 0; r < 32; r += 8) {
        const int n = r + ty;
        float v0 = t[2 * tx][n], v1 = t[2 * tx + 1][n];
        __nv_bfloat16 h0, l0, h1, l1;
        split2(v0, h0, l0); split2(v1, h1, l1);
        __nv_bfloat162 H; H.x = h0; H.y = h1;
        __nv_bfloat162 L; L.x = l0; L.y = l1;
        size_t o = (size_t)(roff + n0 + n) * ldT + k0 + 2 * tx;
        *reinterpret_cast<__nv_bfloat162*>(Th + o) = H;
        *reinterpret_cast<__nv_bfloat162*>(Tl + o) = L;
    }
}

// ---------------- bias + 0.54*colsum prep ----------------
__global__ void colprep(const float* __restrict__ bmu, const float* __restrict__ bstd,
                        const __nv_bfloat16* __restrict__ Th, const __nv_bfloat16* __restrict__ Tl,
                        int K, float* __restrict__ bcat, float* __restrict__ ccat)
{
    const int n = blockIdx.x;
    if (n < S_) {
        if (threadIdx.x == 0) { bcat[n] = bmu[n]; ccat[n] = 0.0f; }
        return;
    }
    __shared__ float red[256];
    const __nv_bfloat16* rh = Th + (size_t)n * K;
    const __nv_bfloat16* rl = Tl + (size_t)n * K;
    float s = 0.0f;
    for (int k = threadIdx.x; k < K; k += 256)
        s += __bfloat162float(rh[k]) + __bfloat162float(rl[k]);
    red[threadIdx.x] = s;
    __syncthreads();
    for (int st = 128; st; st >>= 1) {
        if (threadIdx.x < st) red[threadIdx.x] += red[threadIdx.x + st];
        __syncthreads();
    }
    if (threadIdx.x == 0) { bcat[n] = bstd[n - S_]; ccat[n] = 0.54f * red[0]; }
}

// ---------------- fp32 -> split bf16, vectorized x4 ----------------
__global__ void split_convert4(const float* __restrict__ src, int srcW,
                               __nv_bfloat16* __restrict__ dh, __nv_bfloat16* __restrict__ dl,
                               int dstW, int coff)
{
    int idx = blockIdx.x * 256 + threadIdx.x;
    int e = idx * 4;
    int b = e / srcW, j = e - b * srcW;
    float4 v = *reinterpret_cast<const float4*>(src + e);
    __nv_bfloat16 h0,l0,h1,l1,h2,l2,h3,l3;
    split2(v.x,h0,l0); split2(v.y,h1,l1); split2(v.z,h2,l2); split2(v.w,h3,l3);
    __nv_bfloat162 H0; H0.x=h0; H0.y=h1;
    __nv_bfloat162 H1; H1.x=h2; H1.y=h3;
    __nv_bfloat162 L0; L0.x=l0; L0.y=l1;
    __nv_bfloat162 L1; L1.x=l2; L1.y=l3;
    size_t o = (size_t)b * dstW + coff + j;
    *reinterpret_cast<__nv_bfloat162*>(dh + o) = H0;
    *reinterpret_cast<__nv_bfloat162*>(dh + o + 2) = H1;
    *reinterpret_cast<__nv_bfloat162*>(dl + o) = L0;
    *reinterpret_cast<__nv_bfloat162*>(dl + o + 2) = L1;
}

// ---------------- GRU gates, vectorized x2 ----------------
__global__ void gru_gate_k(const float* __restrict__ gi, const float* __restrict__ gh,
                           const float* __restrict__ h,
                           float* __restrict__ outdet,
                           __nv_bfloat16* __restrict__ dh, __nv_bfloat16* __restrict__ dl,
                           __nv_bfloat16* __restrict__ xh, __nv_bfloat16* __restrict__ xl)
{
    const int idx = blockIdx.x * 256 + threadIdx.x;
    const int e = idx * 2;
    const int b = e >> 11;
    const int j = e & (D_ - 1);
    const float* gib = gi + (size_t)b * 3 * D_;
    const float* ghb = gh + (size_t)b * 3 * D_;
    float2 giz = *reinterpret_cast<const float2*>(gib + j);
    float2 gir = *reinterpret_cast<const float2*>(gib + D_ + j);
    float2 gih = *reinterpret_cast<const float2*>(gib + 2 * D_ + j);
    float2 ghz = *reinterpret_cast<const float2*>(ghb + j);
    float2 ghr = *reinterpret_cast<const float2*>(ghb + D_ + j);
    float2 ghh = *reinterpret_cast<const float2*>(ghb + 2 * D_ + j);
    float2 hv  = *reinterpret_cast<const float2*>(h + e);
    float z0 = sigmoidf_(giz.x + ghz.x), z1 = sigmoidf_(giz.y + ghz.y);
    float r0 = sigmoidf_(gir.x + ghr.x), r1 = sigmoidf_(gir.y + ghr.y);
    float n0 = tanhf(gih.x + r0 * ghh.x), n1 = tanhf(gih.y + r1 * ghh.y);
    float v0 = z0 * hv.x + (1.0f - z0) * n0;
    float v1 = z1 * hv.y + (1.0f - z1) * n1;
    if (outdet) {
        float2 o; o.x = v0; o.y = v1;
        *reinterpret_cast<float2*>(outdet + (size_t)b * OUTW + j) = o;
    }
    __nv_bfloat16 h0,l0,h1,l1;
    split2(v0,h0,l0); split2(v1,h1,l1);
    __nv_bfloat162 H; H.x=h0; H.y=h1;
    __nv_bfloat162 L; L.x=l0; L.y=l1;
    *reinterpret_cast<__nv_bfloat162*>(dh + e) = H;
    *reinterpret_cast<__nv_bfloat162*>(dl + e) = L;
    if (xh) {
        *reinterpret_cast<__nv_bfloat162*>(xh + (size_t)b * 4096 + j) = H;
        *reinterpret_cast<__nv_bfloat162*>(xl + (size_t)b * 4096 + j) = L;
    }
}

// ---------------- sample = mu + std * eps, vectorized x2 ----------------
__global__ void sample_k(float* __restrict__ out, int off_mu, int off_std, int off_s,
                         const float* __restrict__ eps)
{
    const int idx = blockIdx.x * 256 + threadIdx.x;
    const int e = idx * 2;
    const int b = e >> 10;
    const int j = e & (S_ - 1);
    float* row = out + (size_t)b * OUTW;
    float2 mu = *reinterpret_cast<const float2*>(row + off_mu + j);
    float2 sd = *reinterpret_cast<const float2*>(row + off_std + j);
    float2 ep = *reinterpret_cast<const float2*>(eps + e);
    float2 o; o.x = mu.x + sd.x * ep.x; o.y = mu.y + sd.y * ep.y;
    *reinterpret_cast<float2*>(row + off_s + j) = o;
}

// ---------------- launch ----------------
extern "C" void kernel_launch(void* const* d_in, const int* in_sizes, int n_in,
                              void* d_out, int out_size)
{
    const float* obs         = (const float*)d_in[0];
    const float* context     = (const float*)d_in[1];
    const float* prev_sample = (const float*)d_in[2];
    const float* prev_h      = (const float*)d_in[3];
    const float* eps_prior   = (const float*)d_in[5];
    const float* eps_post    = (const float*)d_in[6];
    const float* W_p1  = (const float*)d_in[7];
    const float* b_p1  = (const float*)d_in[8];
    const float* Wi    = (const float*)d_in[9];
    const float* Wh    = (const float*)d_in[10];
    const float* bi    = (const float*)d_in[11];
    const float* bh    = (const float*)d_in[12];
    const float* W_p2  = (const float*)d_in[13];
    const float* b_p2  = (const float*)d_in[14];
    const float* W_pmu = (const float*)d_in[15];
    const float* b_pmu = (const float*)d_in[16];
    const float* W_pstd= (const float*)d_in[17];
    const float* b_pstd= (const float*)d_in[18];
    const float* W_q1  = (const float*)d_in[19];
    const float* b_q1  = (const float*)d_in[20];
    const float* W_q2  = (const float*)d_in[21];
    const float* b_q2  = (const float*)d_in[22];
    const float* W_qmu = (const float*)d_in[23];
    const float* b_qmu = (const float*)d_in[24];
    const float* W_qstd= (const float*)d_in[25];
    const float* b_qstd= (const float*)d_in[26];
    float* out = (float*)d_out;

    static cudaStream_t s1 = nullptr, s2 = nullptr;
    static cudaEvent_t evRoot, evWi, evGh, evGru, evC, evP2, evPrior, evXq;
    if (!s1) {
        cudaStreamCreateWithFlags(&s1, cudaStreamNonBlocking);
        cudaStreamCreateWithFlags(&s2, cudaStreamNonBlocking);
        cudaEventCreateWithFlags(&evRoot,  cudaEventDisableTiming);
        cudaEventCreateWithFlags(&evWi,    cudaEventDisableTiming);
        cudaEventCreateWithFlags(&evGh,    cudaEventDisableTiming);
        cudaEventCreateWithFlags(&evGru,   cudaEventDisableTiming);
        cudaEventCreateWithFlags(&evC,     cudaEventDisableTiming);
        cudaEventCreateWithFlags(&evP2,    cudaEventDisableTiming);
        cudaEventCreateWithFlags(&evPrior, cudaEventDisableTiming);
        cudaEventCreateWithFlags(&evXq,    cudaEventDisableTiming);
    }
    cudaFuncSetAttribute(gemm_mma, cudaFuncAttributeMaxDynamicSharedMemorySize, SMEMB);

#define SYM(p, s) float* p; cudaGetSymbolAddress((void**)&p, s)
#define SYMB(p, s) __nv_bfloat16* p; cudaGetSymbolAddress((void**)&p, s)
    SYMB(Wp1h,g_Wp1h); SYMB(Wp1l,g_Wp1l); SYMB(Wih,g_Wih); SYMB(Wil,g_Wil);
    SYMB(Whh,g_Whh); SYMB(Whl,g_Whl); SYMB(Wp2h,g_Wp2h); SYMB(Wp2l,g_Wp2l);
    SYMB(Wcph,g_Wcph); SYMB(Wcpl,g_Wcpl); SYMB(Wq1h,g_Wq1h); SYMB(Wq1l,g_Wq1l);
    SYMB(Wq2h,g_Wq2h); SYMB(Wq2l,g_Wq2l); SYMB(Wcqh,g_Wcqh); SYMB(Wcql,g_Wcql);
    SYMB(Xh,g_Xh); SYMB(Xl,g_Xl); SYMB(Ph,g_Ph); SYMB(Pl,g_Pl);
    SYMB(h1h,g_h1h); SYMB(h1l,g_h1l); SYMB(dth,g_dth); SYMB(dtl,g_dtl);
    SYMB(h2h,g_h2h); SYMB(h2l,g_h2l); SYMB(h2qh,g_h2qh); SYMB(h2ql,g_h2ql);
    SYMB(Xqh,g_Xqh); SYMB(Xql,g_Xql); SYMB(dqh,g_dqh); SYMB(dql,g_dql);
    SYM(giF,g_gi); SYM(ghF,g_gh);
    SYM(bcp,g_bcp); SYM(ccp,g_ccp); SYM(bcq,g_bcq); SYM(ccq,g_ccq);
#undef SYM
#undef SYMB

    const dim3 tb(32, 8);
    const dim3 gN2(2048 / TN, B_ / TM);   // (32, 16)
    const dim3 gN6(6144 / TN, B_ / TM);   // (96, 16)

    cudaEventRecord(evRoot, 0);
    cudaStreamWaitEvent(s1, evRoot, 0);
    cudaStreamWaitEvent(s2, evRoot, 0);

    // ---- s0: p1 prep + p1 GEMM (GEMM = 4th launch, keeps ncu on the GEMM) ----
    split_convert4<<<1024, 256, 0, 0>>>(prev_sample, 1024, Xh, Xl, 2048, 0);
    split_convert4<<<1024, 256, 0, 0>>>(context,     1024, Xh, Xl, 2048, 1024);
    transpose_split<<<dim3(64, 32), tb, 0, 0>>>(W_p1, 2048, 2048, Wp1h, Wp1l, 2048, 0);
    gemm_mma<<<gN2, 128, SMEMB, 0>>>(Xh, Xl, Wp1h, Wp1l, b_p1, nullptr,
        nullptr, h1h, h1l, 2048, 2048, 1);

    // ---- s1: GRU-h prep + gh GEMM ----
    split_convert4<<<2048, 256, 0, s1>>>(prev_h, 2048, Ph, Pl, 2048, 0);
    transpose_split<<<dim3(192, 32), tb, 0, s1>>>(Wh, 2048, 6144, Whh, Whl, 2048, 0);
    gemm_mma<<<gN6, 128, SMEMB, s1>>>(Ph, Pl, Whh, Whl, bh, nullptr,
        ghF, nullptr, nullptr, 2048, 6144, 0);
    cudaEventRecord(evGh, s1);

    // ---- s2: remaining prep ----
    transpose_split<<<dim3(192, 32), tb, 0, s2>>>(Wi, 2048, 6144, Wih, Wil, 2048, 0);
    cudaEventRecord(evWi, s2);
    split_convert4<<<2048, 256, 0, s2>>>(obs, 2048, Xqh, Xql, 4096, 2048);
    cudaEventRecord(evXq, s2);
    transpose_split<<<dim3(64, 64), tb, 0, s2>>>(W_q1, 4096, 2048, Wq1h, Wq1l, 4096, 0);
    transpose_split<<<dim3(64, 32), tb, 0, s2>>>(W_q2, 2048, 2048, Wq2h, Wq2l, 2048, 0);
    transpose_split<<<dim3(32, 32), tb, 0, s2>>>(W_qmu, 2048, 1024, Wcqh, Wcql, 2048, 0);
    transpose_split<<<dim3(32, 32), tb, 0, s2>>>(W_qstd,2048, 1024, Wcqh, Wcql, 2048, 1024);
    colprep<<<2048, 256, 0, s2>>>(b_qmu, b_qstd, Wcqh, Wcql, 2048, bcq, ccq);
    cudaEventRecord(evC, s2);
    transpose_split<<<dim3(64, 32), tb, 0, s2>>>(W_p2, 2048, 2048, Wp2h, Wp2l, 2048, 0);
    transpose_split<<<dim3(32, 32), tb, 0, s2>>>(W_pmu, 2048, 1024, Wcph, Wcpl, 2048, 0);
    transpose_split<<<dim3(32, 32), tb, 0, s2>>>(W_pstd,2048, 1024, Wcph, Wcpl, 2048, 1024);
    colprep<<<2048, 256, 0, s2>>>(b_pmu, b_pstd, Wcph, Wcpl, 2048, bcp, ccp);
    cudaEventRecord(evP2, s2);

    // ---- s0: prior chain ----
    cudaStreamWaitEvent(0, evWi, 0);
    gemm_mma<<<gN6, 128, SMEMB, 0>>>(h1h, h1l, Wih, Wil, bi, nullptr,
        giF, nullptr, nullptr, 2048, 6144, 0);
    cudaStreamWaitEvent(0, evGh, 0);
    cudaStreamWaitEvent(0, evXq, 0);
    gru_gate_k<<<(B_ * D_) / 512, 256, 0, 0>>>(giF, ghF, prev_h, out + 3 * S_, dth, dtl, Xqh, Xql);
    cudaEventRecord(evGru, 0);

    // ---- s1: prior tail ----
    cudaStreamWaitEvent(s1, evGru, 0);
    cudaStreamWaitEvent(s1, evP2, 0);
    gemm_mma<<<gN2, 128, SMEMB, s1>>>(dth, dtl, Wp2h, Wp2l, b_p2, nullptr,
        nullptr, h2h, h2l, 2048, 2048, 1);
    gemm_mma<<<gN2, 128, SMEMB, s1>>>(h2h, h2l, Wcph, Wcpl, bcp, ccp,
        out, nullptr, nullptr, 2048, OUTW, 2);
    sample_k<<<(B_ * S_) / 512, 256, 0, s1>>>(out, 0, S_, 2 * S_, eps_prior);
    cudaEventRecord(evPrior, s1);

    // ---- s0: posterior chain ----
    cudaStreamWaitEvent(0, evC, 0);
    gemm_mma<<<gN2, 128, SMEMB, 0>>>(Xqh, Xql, Wq1h, Wq1l, b_q1, nullptr,
        nullptr, h1h, h1l, 4096, 2048, 1);
    gemm_mma<<<gN6, 128, SMEMB, 0>>>(h1h, h1l, Wih, Wil, bi, nullptr,
        giF, nullptr, nullptr, 2048, 6144, 0);
    gru_gate_k<<<(B_ * D_) / 512, 256, 0, 0>>>(giF, ghF, prev_h, nullptr, dqh, dql, nullptr, nullptr);
    gemm_mma<<<gN2, 128, SMEMB, 0>>>(dqh, dql, Wq2h, Wq2l, b_q2, nullptr,
        nullptr, h2qh, h2ql, 2048, 2048, 1);
    gemm_mma<<<gN2, 128, SMEMB, 0>>>(h2qh, h2ql, Wcqh, Wcql, bcq, ccq,
        out + 5 * S_, nullptr, nullptr, 2048, OUTW, 2);
    sample_k<<<(B_ * S_) / 512, 256, 0, 0>>>(out, 5 * S_, 6 * S_, 7 * S_, eps_post);

    cudaStreamWaitEvent(0, evPrior, 0);

    (void)in_sizes; (void)n_in; (void)out_size;
}

// round 16
// speedup vs baseline: 1.3801x; 1.3801x over previous
#include <cuda_runtime.h>
#include <cuda_bf16.h>
#include <math.h>
#include <stdint.h>

#define B_   1024
#define S_   1024
#define D_   2048
#define E_   2048
#define OUTW 8192

#define TM 64
#define TN 64
#define KC 32
#define NSTAGE 3
// stage: A_hi 4KB + A_lo 4KB + B_hi 4KB + B_lo 4KB = 16KB
#define ATILE 4096u
#define BTILE 4096u
#define SB_H  (2u * ATILE)
#define SB_L  (2u * ATILE + BTILE)
#define STG   (2u * ATILE + 2u * BTILE)
#define SMEMB ((int)(NSTAGE * STG))

// ---------------- device scratch ----------------
__device__ __align__(128) __nv_bfloat16 g_Wp1h[2048u*2048u], g_Wp1l[2048u*2048u];
__device__ __align__(128) __nv_bfloat16 g_Wih [6144u*2048u], g_Wil [6144u*2048u];
__device__ __align__(128) __nv_bfloat16 g_Whh [6144u*2048u], g_Whl [6144u*2048u];
__device__ __align__(128) __nv_bfloat16 g_Wp2h[2048u*2048u], g_Wp2l[2048u*2048u];
__device__ __align__(128) __nv_bfloat16 g_Wcph[2048u*2048u], g_Wcpl[2048u*2048u];
__device__ __align__(128) __nv_bfloat16 g_Wq1h[2048u*4096u], g_Wq1l[2048u*4096u];
__device__ __align__(128) __nv_bfloat16 g_Wq2h[2048u*2048u], g_Wq2l[2048u*2048u];
__device__ __align__(128) __nv_bfloat16 g_Wcqh[2048u*2048u], g_Wcql[2048u*2048u];
__device__ __align__(128) __nv_bfloat16 g_Xh [B_*2048u], g_Xl [B_*2048u];
__device__ __align__(128) __nv_bfloat16 g_Ph [B_*2048u], g_Pl [B_*2048u];
__device__ __align__(128) __nv_bfloat16 g_h1h[B_*2048u], g_h1l[B_*2048u];
__device__ __align__(128) __nv_bfloat16 g_dth[B_*2048u], g_dtl[B_*2048u];
__device__ __align__(128) __nv_bfloat16 g_h2h[B_*2048u], g_h2l[B_*2048u];
__device__ __align__(128) __nv_bfloat16 g_h2qh[B_*2048u], g_h2ql[B_*2048u];
__device__ __align__(128) __nv_bfloat16 g_Xqh[B_*4096u], g_Xql[B_*4096u];
__device__ __align__(128) __nv_bfloat16 g_dqh[B_*2048u], g_dql[B_*2048u];
__device__ __align__(128) float g_gi[B_*6144u];
__device__ __align__(128) float g_gh[B_*6144u];
__device__ __align__(128) float g_bcp[2048], g_ccp[2048], g_bcq[2048], g_ccq[2048];

// ---------------- helpers ----------------
__device__ __forceinline__ float sigmoidf_(float x) { return 1.0f / (1.0f + expf(-x)); }
__device__ __forceinline__ float softplusf_(float x) {
    return fmaxf(x, 0.0f) + log1pf(expf(-fabsf(x)));
}
__device__ __forceinline__ void split2(float v, __nv_bfloat16& h, __nv_bfloat16& l) {
    h = __float2bfloat16(v);
    l = __float2bfloat16(v - __bfloat162float(h));
}
__device__ __forceinline__ uint32_t smem_u32(const void* p) {
    uint32_t a;
    asm("{ .reg .u64 t; cvta.to.shared.u64 t, %1; cvt.u32.u64 %0, t; }" : "=r"(a) : "l"(p));
    return a;
}
__device__ __forceinline__ void cp16(uint32_t s, const void* g) {
    asm volatile("cp.async.cg.shared.global [%0], [%1], 16;" :: "r"(s), "l"(g));
}
__device__ __forceinline__ void cpcommit() { asm volatile("cp.async.commit_group;" ::: "memory"); }
__device__ __forceinline__ void cpwait1() { asm volatile("cp.async.wait_group 1;" ::: "memory"); }
__device__ __forceinline__ void cpwait0() { asm volatile("cp.async.wait_group 0;" ::: "memory"); }
__device__ __forceinline__ void ldm_x4(uint32_t* r, uint32_t addr) {
    asm volatile("ldmatrix.sync.aligned.m8n8.x4.shared.b16 {%0,%1,%2,%3}, [%4];"
                 : "=r"(r[0]), "=r"(r[1]), "=r"(r[2]), "=r"(r[3]) : "r"(addr));
}
__device__ __forceinline__ void mma_bf16(float* c, const uint32_t* a, const uint32_t* b) {
    asm volatile(
        "mma.sync.aligned.m16n8k16.row.col.f32.bf16.bf16.f32 "
        "{%0,%1,%2,%3}, {%4,%5,%6,%7}, {%8,%9}, {%0,%1,%2,%3};"
        : "+f"(c[0]), "+f"(c[1]), "+f"(c[2]), "+f"(c[3])
        : "r"(a[0]), "r"(a[1]), "r"(a[2]), "r"(a[3]), "r"(b[0]), "r"(b[1]));
}
__device__ __forceinline__ uint32_t tadr(int row, int kc) {
    return (uint32_t)(row * 64) + (uint32_t)((kc ^ ((row >> 1) & 3)) << 4);
}

// ---------------- split-bf16 HMMA GEMM: 64x64 tile, 128 thr, 4 CTA/SM (R10) ----------------
// epi: 0 fp32->Cf ; 1 relu->split bf16 (Chi,Clo) ; 2 fused mu/std -> Cf
__global__ void __launch_bounds__(128, 4) gemm_mma(
    const __nv_bfloat16* __restrict__ Ah, const __nv_bfloat16* __restrict__ Al,
    const __nv_bfloat16* __restrict__ Bh, const __nv_bfloat16* __restrict__ Bl,
    const float* __restrict__ bias, const float* __restrict__ csum,
    float* __restrict__ Cf, __nv_bfloat16* __restrict__ Chi, __nv_bfloat16* __restrict__ Clo,
    int K, int ldc, int epi)
{
    extern __shared__ __align__(1024) char smem[];
    const uint32_t sb = smem_u32(smem);
    const int tid = threadIdx.x;
    const int lane = tid & 31, wid = tid >> 5;
    const int wr = wid >> 1, wc = wid & 1;
    const int bm = blockIdx.y * TM;
    const int bn = blockIdx.x * TN;
    const int g = lane >> 3, i8 = lane & 7;

    float acc[2][4][4];
#pragma unroll
    for (int a = 0; a < 2; a++)
#pragma unroll
        for (int b = 0; b < 4; b++)
#pragma unroll
            for (int k = 0; k < 4; k++) acc[a][b][k] = 0.0f;

    auto load_stage = [&](uint32_t sbase, int kpos) {
#pragma unroll
        for (int q = tid; q < 256; q += 128) {
            int row = q >> 2, kc = q & 3;
            uint32_t so = tadr(row, kc);
            size_t goA = (size_t)(bm + row) * K + kpos + kc * 8;
            size_t goB = (size_t)(bn + row) * K + kpos + kc * 8;
            cp16(sbase + so, Ah + goA);
            cp16(sbase + ATILE + so, Al + goA);
            cp16(sbase + SB_H + so, Bh + goB);
            cp16(sbase + SB_L + so, Bl + goB);
        }
        cpcommit();
    };

    load_stage(sb, 0);
    load_stage(sb + STG, KC);

    const int nk = K / KC;
    const int aRowBase = wr * 32 + (g & 1) * 8 + i8;
    const int aKsel = g >> 1;
    const int bRowBase = wc * 32 + (g >> 1) * 8 + i8;
    const int bKsel = g & 1;

    int bufc = 0, bufl = 2;
    for (int s = 0; s < nk; s++) {
        if (s < nk - 1) cpwait1(); else cpwait0();
        __syncthreads();
        if (s + 2 < nk) load_stage(sb + (uint32_t)bufl * STG, (s + 2) * KC);

        const uint32_t base = sb + (uint32_t)bufc * STG;
        const uint32_t bAh = base, bAl = base + ATILE;
        const uint32_t bBh = base + SB_H, bBl = base + SB_L;

#pragma unroll
        for (int step = 0; step < 2; step++) {
            const int c0 = step * 2;
            uint32_t Bfh[4][2], Bfl[4][2];
#pragma unroll
            for (int half = 0; half < 2; half++) {
                uint32_t r[4];
                int nrow = bRowBase + half * 16;
                int kc = c0 + bKsel;
                ldm_x4(r, bBh + tadr(nrow, kc));
                Bfh[half * 2 + 0][0] = r[0]; Bfh[half * 2 + 0][1] = r[1];
                Bfh[half * 2 + 1][0] = r[2]; Bfh[half * 2 + 1][1] = r[3];
                ldm_x4(r, bBl + tadr(nrow, kc));
                Bfl[half * 2 + 0][0] = r[0]; Bfl[half * 2 + 0][1] = r[1];
                Bfl[half * 2 + 1][0] = r[2]; Bfl[half * 2 + 1][1] = r[3];
            }
#pragma unroll
            for (int am = 0; am < 2; am++) {
                uint32_t Afh[4], Afl[4];
                int arow = aRowBase + am * 16;
                int kc = c0 + aKsel;
                ldm_x4(Afh, bAh + tadr(arow, kc));
                ldm_x4(Afl, bAl + tadr(arow, kc));
#pragma unroll
                for (int bnf = 0; bnf < 4; bnf++) mma_bf16(acc[am][bnf], Afh, Bfh[bnf]);
#pragma unroll
                for (int bnf = 0; bnf < 4; bnf++) mma_bf16(acc[am][bnf], Afh, Bfl[bnf]);
#pragma unroll
                for (int bnf = 0; bnf < 4; bnf++) mma_bf16(acc[am][bnf], Afl, Bfh[bnf]);
            }
        }
        bufc = (bufc == 2) ? 0 : bufc + 1;
        bufl = (bufl == 2) ? 0 : bufl + 1;
    }

    const int rQ = lane >> 2;
    const int cP = (lane & 3) * 2;
#pragma unroll
    for (int am = 0; am < 2; am++) {
#pragma unroll
        for (int bnf = 0; bnf < 4; bnf++) {
            const int r0 = bm + wr * 32 + am * 16 + rQ;
            const int c  = bn + wc * 32 + bnf * 8 + cP;
            float v0 = acc[am][bnf][0] + bias[c];
            float v1 = acc[am][bnf][1] + bias[c + 1];
            float v2 = acc[am][bnf][2] + bias[c];
            float v3 = acc[am][bnf][3] + bias[c + 1];
            if (epi == 1) {
                v0 = fmaxf(v0, 0.0f); v1 = fmaxf(v1, 0.0f);
                v2 = fmaxf(v2, 0.0f); v3 = fmaxf(v3, 0.0f);
                __nv_bfloat16 h0,l0,h1,l1,h2,l2,h3,l3;
                split2(v0,h0,l0); split2(v1,h1,l1); split2(v2,h2,l2); split2(v3,h3,l3);
                __nv_bfloat162 p01; p01.x = h0; p01.y = h1;
                __nv_bfloat162 q01; q01.x = l0; q01.y = l1;
                __nv_bfloat162 p23; p23.x = h2; p23.y = h3;
                __nv_bfloat162 q23; q23.x = l2; q23.y = l3;
                *reinterpret_cast<__nv_bfloat162*>(Chi + (size_t)r0 * ldc + c) = p01;
                *reinterpret_cast<__nv_bfloat162*>(Clo + (size_t)r0 * ldc + c) = q01;
                *reinterpret_cast<__nv_bfloat162*>(Chi + (size_t)(r0 + 8) * ldc + c) = p23;
                *reinterpret_cast<__nv_bfloat162*>(Clo + (size_t)(r0 + 8) * ldc + c) = q23;
            } else {
                if (epi == 2 && c >= S_) {
                    const float cs0 = csum[c], cs1 = csum[c + 1];
                    v0 = softplusf_(v0 + cs0) + 1e-4f;
                    v1 = softplusf_(v1 + cs1) + 1e-4f;
                    v2 = softplusf_(v2 + cs0) + 1e-4f;
                    v3 = softplusf_(v3 + cs1) + 1e-4f;
                }
                float2 w01; w01.x = v0; w01.y = v1;
                float2 w23; w23.x = v2; w23.y = v3;
                *reinterpret_cast<float2*>(Cf + (size_t)r0 * ldc + c) = w01;
                *reinterpret_cast<float2*>(Cf + (size_t)(r0 + 8) * ldc + c) = w23;
            }
        }
    }
}

// ---------------- transpose + split (vectorized) ----------------
__global__ void transpose_split(const float* __restrict__ W, int K, int N,
                                __nv_bfloat16* __restrict__ Th, __nv_bfloat16* __restrict__ Tl,
                                int ldT, int roff)
{
    __shared__ float t[64][33];
    const int n0 = blockIdx.x * 32, k0 = blockIdx.y * 64;
    const int tx = threadIdx.x, ty = threadIdx.y;
#pragma unroll
    for (int r = 0; r < 64; r += 8)
        t[ty + r][tx] = W[(size_t)(k0 + ty + r) * N + n0 + tx];
    __syncthreads();
#pragma unroll
    for (int r = 0; r < 32; r += 8) {
        const int n = r + ty;
        float v0 = t[2 * tx][n], v1 = t[2 * tx + 1][n];
        __nv_bfloat16 h0, l0, h1, l1;
        split2(v0, h0, l0); split2(v1, h1, l1);
        __nv_bfloat162 H; H.x = h0; H.y = h1;
        __nv_bfloat162 L; L.x = l0; L.y = l1;
        size_t o = (size_t)(roff + n0 + n) * ldT + k0 + 2 * tx;
        *reinterpret_cast<__nv_bfloat162*>(Th + o) = H;
        *reinterpret_cast<__nv_bfloat162*>(Tl + o) = L;
    }
}

// ---------------- bias + 0.54*colsum prep ----------------
__global__ void colprep(const float* __restrict__ bmu, const float* __restrict__ bstd,
                        const __nv_bfloat16* __restrict__ Th, const __nv_bfloat16* __restrict__ Tl,
                        int K, float* __restrict__ bcat, float* __restrict__ ccat)
{
    const int n = blockIdx.x;
    if (n < S_) {
        if (threadIdx.x == 0) { bcat[n] = bmu[n]; ccat[n] = 0.0f; }
        return;
    }
    __shared__ float red[256];
    const __nv_bfloat16* rh = Th + (size_t)n * K;
    const __nv_bfloat16* rl = Tl + (size_t)n * K;
    float s = 0.0f;
    for (int k = threadIdx.x; k < K; k += 256)
        s += __bfloat162float(rh[k]) + __bfloat162float(rl[k]);
    red[threadIdx.x] = s;
    __syncthreads();
    for (int st = 128; st; st >>= 1) {
        if (threadIdx.x < st) red[threadIdx.x] += red[threadIdx.x + st];
        __syncthreads();
    }
    if (threadIdx.x == 0) { bcat[n] = bstd[n - S_]; ccat[n] = 0.54f * red[0]; }
}

// ---------------- fp32 -> split bf16, vectorized x4 ----------------
__global__ void split_convert4(const float* __restrict__ src, int srcW,
                               __nv_bfloat16* __restrict__ dh, __nv_bfloat16* __restrict__ dl,
                               int dstW, int coff)
{
    int idx = blockIdx.x * 256 + threadIdx.x;
    int e = idx * 4;
    int b = e / srcW, j = e - b * srcW;
    float4 v = *reinterpret_cast<const float4*>(src + e);
    __nv_bfloat16 h0,l0,h1,l1,h2,l2,h3,l3;
    split2(v.x,h0,l0); split2(v.y,h1,l1); split2(v.z,h2,l2); split2(v.w,h3,l3);
    __nv_bfloat162 H0; H0.x=h0; H0.y=h1;
    __nv_bfloat162 H1; H1.x=h2; H1.y=h3;
    __nv_bfloat162 L0; L0.x=l0; L0.y=l1;
    __nv_bfloat162 L1; L1.x=l2; L1.y=l3;
    size_t o = (size_t)b * dstW + coff + j;
    *reinterpret_cast<__nv_bfloat162*>(dh + o) = H0;
    *reinterpret_cast<__nv_bfloat162*>(dh + o + 2) = H1;
    *reinterpret_cast<__nv_bfloat162*>(dl + o) = L0;
    *reinterpret_cast<__nv_bfloat162*>(dl + o + 2) = L1;
}

// ---------------- GRU gates, vectorized x2 ----------------
__global__ void gru_gate_k(const float* __restrict__ gi, const float* __restrict__ gh,
                           const float* __restrict__ h,
                           float* __restrict__ outdet,
                           __nv_bfloat16* __restrict__ dh, __nv_bfloat16* __restrict__ dl,
                           __nv_bfloat16* __restrict__ xh, __nv_bfloat16* __restrict__ xl)
{
    const int idx = blockIdx.x * 256 + threadIdx.x;
    const int e = idx * 2;
    const int b = e >> 11;
    const int j = e & (D_ - 1);
    const float* gib = gi + (size_t)b * 3 * D_;
    const float* ghb = gh + (size_t)b * 3 * D_;
    float2 giz = *reinterpret_cast<const float2*>(gib + j);
    float2 gir = *reinterpret_cast<const float2*>(gib + D_ + j);
    float2 gih = *reinterpret_cast<const float2*>(gib + 2 * D_ + j);
    float2 ghz = *reinterpret_cast<const float2*>(ghb + j);
    float2 ghr = *reinterpret_cast<const float2*>(ghb + D_ + j);
    float2 ghh = *reinterpret_cast<const float2*>(ghb + 2 * D_ + j);
    float2 hv  = *reinterpret_cast<const float2*>(h + e);
    float z0 = sigmoidf_(giz.x + ghz.x), z1 = sigmoidf_(giz.y + ghz.y);
    float r0 = sigmoidf_(gir.x + ghr.x), r1 = sigmoidf_(gir.y + ghr.y);
    float n0 = tanhf(gih.x + r0 * ghh.x), n1 = tanhf(gih.y + r1 * ghh.y);
    float v0 = z0 * hv.x + (1.0f - z0) * n0;
    float v1 = z1 * hv.y + (1.0f - z1) * n1;
    if (outdet) {
        float2 o; o.x = v0; o.y = v1;
        *reinterpret_cast<float2*>(outdet + (size_t)b * OUTW + j) = o;
    }
    __nv_bfloat16 h0,l0,h1,l1;
    split2(v0,h0,l0); split2(v1,h1,l1);
    __nv_bfloat162 H; H.x=h0; H.y=h1;
    __nv_bfloat162 L; L.x=l0; L.y=l1;
    *reinterpret_cast<__nv_bfloat162*>(dh + e) = H;
    *reinterpret_cast<__nv_bfloat162*>(dl + e) = L;
    if (xh) {
        *reinterpret_cast<__nv_bfloat162*>(xh + (size_t)b * 4096 + j) = H;
        *reinterpret_cast<__nv_bfloat162*>(xl + (size_t)b * 4096 + j) = L;
    }
}

// ---------------- sample = mu + std * eps, vectorized x2 ----------------
__global__ void sample_k(float* __restrict__ out, int off_mu, int off_std, int off_s,
                         const float* __restrict__ eps)
{
    const int idx = blockIdx.x * 256 + threadIdx.x;
    const int e = idx * 2;
    const int b = e >> 10;
    const int j = e & (S_ - 1);
    float* row = out + (size_t)b * OUTW;
    float2 mu = *reinterpret_cast<const float2*>(row + off_mu + j);
    float2 sd = *reinterpret_cast<const float2*>(row + off_std + j);
    float2 ep = *reinterpret_cast<const float2*>(eps + e);
    float2 o; o.x = mu.x + sd.x * ep.x; o.y = mu.y + sd.y * ep.y;
    *reinterpret_cast<float2*>(row + off_s + j) = o;
}

// ---------------- launch ----------------
extern "C" void kernel_launch(void* const* d_in, const int* in_sizes, int n_in,
                              void* d_out, int out_size)
{
    const float* obs         = (const float*)d_in[0];
    const float* context     = (const float*)d_in[1];
    const float* prev_sample = (const float*)d_in[2];
    const float* prev_h      = (const float*)d_in[3];
    const float* eps_prior   = (const float*)d_in[5];
    const float* eps_post    = (const float*)d_in[6];
    const float* W_p1  = (const float*)d_in[7];
    const float* b_p1  = (const float*)d_in[8];
    const float* Wi    = (const float*)d_in[9];
    const float* Wh    = (const float*)d_in[10];
    const float* bi    = (const float*)d_in[11];
    const float* bh    = (const float*)d_in[12];
    const float* W_p2  = (const float*)d_in[13];
    const float* b_p2  = (const float*)d_in[14];
    const float* W_pmu = (const float*)d_in[15];
    const float* b_pmu = (const float*)d_in[16];
    const float* W_pstd= (const float*)d_in[17];
    const float* b_pstd= (const float*)d_in[18];
    const float* W_q1  = (const float*)d_in[19];
    const float* b_q1  = (const float*)d_in[20];
    const float* W_q2  = (const float*)d_in[21];
    const float* b_q2  = (const float*)d_in[22];
    const float* W_qmu = (const float*)d_in[23];
    const float* b_qmu = (const float*)d_in[24];
    const float* W_qstd= (const float*)d_in[25];
    const float* b_qstd= (const float*)d_in[26];
    float* out = (float*)d_out;

    static cudaStream_t s1 = nullptr, s2 = nullptr;
    static cudaEvent_t evRoot, evWi, evGh, evGru, evC, evP2, evPrior, evXq, evWq1, evWq2;
    if (!s1) {
        cudaStreamCreateWithFlags(&s1, cudaStreamNonBlocking);
        cudaStreamCreateWithFlags(&s2, cudaStreamNonBlocking);
        cudaEvent_t* evs[] = {&evRoot,&evWi,&evGh,&evGru,&evC,&evP2,&evPrior,&evXq,&evWq1,&evWq2};
        for (auto e : evs) cudaEventCreateWithFlags(e, cudaEventDisableTiming);
    }
    cudaFuncSetAttribute(gemm_mma, cudaFuncAttributeMaxDynamicSharedMemorySize, SMEMB);

#define SYM(p, s) float* p; cudaGetSymbolAddress((void**)&p, s)
#define SYMB(p, s) __nv_bfloat16* p; cudaGetSymbolAddress((void**)&p, s)
    SYMB(Wp1h,g_Wp1h); SYMB(Wp1l,g_Wp1l); SYMB(Wih,g_Wih); SYMB(Wil,g_Wil);
    SYMB(Whh,g_Whh); SYMB(Whl,g_Whl); SYMB(Wp2h,g_Wp2h); SYMB(Wp2l,g_Wp2l);
    SYMB(Wcph,g_Wcph); SYMB(Wcpl,g_Wcpl); SYMB(Wq1h,g_Wq1h); SYMB(Wq1l,g_Wq1l);
    SYMB(Wq2h,g_Wq2h); SYMB(Wq2l,g_Wq2l); SYMB(Wcqh,g_Wcqh); SYMB(Wcql,g_Wcql);
    SYMB(Xh,g_Xh); SYMB(Xl,g_Xl); SYMB(Ph,g_Ph); SYMB(Pl,g_Pl);
    SYMB(h1h,g_h1h); SYMB(h1l,g_h1l); SYMB(dth,g_dth); SYMB(dtl,g_dtl);
    SYMB(h2h,g_h2h); SYMB(h2l,g_h2l); SYMB(h2qh,g_h2qh); SYMB(h2ql,g_h2ql);
    SYMB(Xqh,g_Xqh); SYMB(Xql,g_Xql); SYMB(dqh,g_dqh); SYMB(dql,g_dql);
    SYM(giF,g_gi); SYM(ghF,g_gh);
    SYM(bcp,g_bcp); SYM(ccp,g_ccp); SYM(bcq,g_bcq); SYM(ccq,g_ccq);
#undef SYM
#undef SYMB

    const dim3 tb(32, 8);
    const dim3 gN2(2048 / TN, B_ / TM);   // (32, 16)
    const dim3 gN6(6144 / TN, B_ / TM);   // (96, 16)

    cudaEventRecord(evRoot, 0);
    cudaStreamWaitEvent(s1, evRoot, 0);
    cudaStreamWaitEvent(s2, evRoot, 0);

    // ---- s0: p1 prep + p1 GEMM (GEMM = 4th launch, keeps ncu on the GEMM) ----
    split_convert4<<<1024, 256, 0, 0>>>(prev_sample, 1024, Xh, Xl, 2048, 0);
    split_convert4<<<1024, 256, 0, 0>>>(context,     1024, Xh, Xl, 2048, 1024);
    transpose_split<<<dim3(64, 32), tb, 0, 0>>>(W_p1, 2048, 2048, Wp1h, Wp1l, 2048, 0);
    gemm_mma<<<gN2, 128, SMEMB, 0>>>(Xh, Xl, Wp1h, Wp1l, b_p1, nullptr,
        nullptr, h1h, h1l, 2048, 2048, 1);

    // ---- s1: GRU-h prep + gh GEMM ----
    split_convert4<<<2048, 256, 0, s1>>>(prev_h, 2048, Ph, Pl, 2048, 0);
    transpose_split<<<dim3(192, 32), tb, 0, s1>>>(Wh, 2048, 6144, Whh, Whl, 2048, 0);
    gemm_mma<<<gN6, 128, SMEMB, s1>>>(Ph, Pl, Whh, Whl, bh, nullptr,
        ghF, nullptr, nullptr, 2048, 6144, 0);
    cudaEventRecord(evGh, s1);

    // ---- s2: remaining prep ----
    transpose_split<<<dim3(192, 32), tb, 0, s2>>>(Wi, 2048, 6144, Wih, Wil, 2048, 0);
    cudaEventRecord(evWi, s2);
    split_convert4<<<2048, 256, 0, s2>>>(obs, 2048, Xqh, Xql, 4096, 2048);
    cudaEventRecord(evXq, s2);
    transpose_split<<<dim3(64, 64), tb, 0, s2>>>(W_q1, 4096, 2048, Wq1h, Wq1l, 4096, 0);
    cudaEventRecord(evWq1, s2);
    transpose_split<<<dim3(64, 32), tb, 0, s2>>>(W_q2, 2048, 2048, Wq2h, Wq2l, 2048, 0);
    cudaEventRecord(evWq2, s2);
    transpose_split<<<dim3(32, 32), tb, 0, s2>>>(W_qmu, 2048, 1024, Wcqh, Wcql, 2048, 0);
    transpose_split<<<dim3(32, 32), tb, 0, s2>>>(W_qstd,2048, 1024, Wcqh, Wcql, 2048, 1024);
    colprep<<<2048, 256, 0, s2>>>(b_qmu, b_qstd, Wcqh, Wcql, 2048, bcq, ccq);
    cudaEventRecord(evC, s2);
    transpose_split<<<dim3(64, 32), tb, 0, s2>>>(W_p2, 2048, 2048, Wp2h, Wp2l, 2048, 0);
    transpose_split<<<dim3(32, 32), tb, 0, s2>>>(W_pmu, 2048, 1024, Wcph, Wcpl, 2048, 0);
    transpose_split<<<dim3(32, 32), tb, 0, s2>>>(W_pstd,2048, 1024, Wcph, Wcpl, 2048, 1024);
    colprep<<<2048, 256, 0, s2>>>(b_pmu, b_pstd, Wcph, Wcpl, 2048, bcp, ccp);
    cudaEventRecord(evP2, s2);

    // ---- s0: prior chain ----
    cudaStreamWaitEvent(0, evWi, 0);
    gemm_mma<<<gN6, 128, SMEMB, 0>>>(h1h, h1l, Wih, Wil, bi, nullptr,
        giF, nullptr, nullptr, 2048, 6144, 0);
    cudaStreamWaitEvent(0, evGh, 0);
    cudaStreamWaitEvent(0, evXq, 0);
    gru_gate_k<<<(B_ * D_) / 512, 256, 0, 0>>>(giF, ghF, prev_h, out + 3 * S_, dth, dtl, Xqh, Xql);
    cudaEventRecord(evGru, 0);

    // ---- s1: prior tail ----
    cudaStreamWaitEvent(s1, evGru, 0);
    cudaStreamWaitEvent(s1, evP2, 0);
    gemm_mma<<<gN2, 128, SMEMB, s1>>>(dth, dtl, Wp2h, Wp2l, b_p2, nullptr,
        nullptr, h2h, h2l, 2048, 2048, 1);
    gemm_mma<<<gN2, 128, SMEMB, s1>>>(h2h, h2l, Wcph, Wcpl, bcp, ccp,
        out, nullptr, nullptr, 2048, OUTW, 2);
    sample_k<<<(B_ * S_) / 512, 256, 0, s1>>>(out, 0, S_, 2 * S_, eps_prior);
    cudaEventRecord(evPrior, s1);

    // ---- s0: posterior chain (fine-grained waits) ----
    cudaStreamWaitEvent(0, evWq1, 0);
    gemm_mma<<<gN2, 128, SMEMB, 0>>>(Xqh, Xql, Wq1h, Wq1l, b_q1, nullptr,
        nullptr, h1h, h1l, 4096, 2048, 1);
    gemm_mma<<<gN6, 128, SMEMB, 0>>>(h1h, h1l, Wih, Wil, bi, nullptr,
        giF, nullptr, nullptr, 2048, 6144, 0);
    gru_gate_k<<<(B_ * D_) / 512, 256, 0, 0>>>(giF, ghF, prev_h, nullptr, dqh, dql, nullptr, nullptr);
    cudaStreamWaitEvent(0, evWq2, 0);
    gemm_mma<<<gN2, 128, SMEMB, 0>>>(dqh, dql, Wq2h, Wq2l, b_q2, nullptr,
        nullptr, h2qh, h2ql, 2048, 2048, 1);
    cudaStreamWaitEvent(0, evC, 0);
    gemm_mma<<<gN2, 128, SMEMB, 0>>>(h2qh, h2ql, Wcqh, Wcql, bcq, ccq,
        out + 5 * S_, nullptr, nullptr, 2048, OUTW, 2);
    sample_k<<<(B_ * S_) / 512, 256, 0, 0>>>(out, 5 * S_, 6 * S_, 7 * S_, eps_post);

    cudaStreamWaitEvent(0, evPrior, 0);

    (void)in_sizes; (void)n_in; (void)out_size;
}